// round 11
// baseline (speedup 1.0000x reference)
#include <cuda_runtime.h>
#include <cuda_fp16.h>
#include <cstdint>
#include <math.h>

// ---------------- problem shapes ----------------
#define B_SZ 4
#define T_SZ 4096
#define C_SZ 2048
#define M_SZ (B_SZ * T_SZ)   // 16384
#define N_SZ (2 * C_SZ)      // 4096
#define K_SZ C_SZ            // 2048

// ---------------- device scratch ----------------
__device__ __half g_gate16[(size_t)M_SZ * C_SZ];
__device__ __half g_val16 [(size_t)M_SZ * C_SZ];
__device__ __half g_a16[(size_t)M_SZ * K_SZ];          // x rounded to fp16
__device__ __half g_b16[(size_t)N_SZ * K_SZ];          // W rounded to fp16

// scan chunk summaries: 32 chunks x 8192 sequences (fp32 for precision)
#define SCAN_CH 128
#define SCAN_NCH (T_SZ / SCAN_CH)   // 32
#define NSEQ (B_SZ * C_SZ)          // 8192
#define NSEQ2 (NSEQ / 2)            // 4096 channel-pairs
__device__ float g_Gc [SCAN_NCH * NSEQ];
__device__ float g_Vc [SCAN_NCH * NSEQ];
__device__ float g_Hin[SCAN_NCH * NSEQ];

// ---------------- helpers ----------------
__device__ __forceinline__ uint32_t smem_u32(const void* p) {
    uint32_t a;
    asm("{ .reg .u64 t; cvta.to.shared.u64 t, %1; cvt.u32.u64 %0, t; }" : "=r"(a) : "l"(p));
    return a;
}
__device__ __forceinline__ void cp16(uint32_t dst, const void* src) {
    asm volatile("cp.async.cg.shared.global [%0], [%1], 16;" :: "r"(dst), "l"(src));
}
#define CP_COMMIT() asm volatile("cp.async.commit_group;" ::: "memory")
#define CP_WAITN(n) asm volatile("cp.async.wait_group %0;" :: "n"(n) : "memory")

#define LDSM4(r0, r1, r2, r3, addr) \
    asm volatile("ldmatrix.sync.aligned.m8n8.x4.shared.b16 {%0,%1,%2,%3}, [%4];" \
        : "=r"(r0), "=r"(r1), "=r"(r2), "=r"(r3) : "r"(addr))

// fp16 inputs, fp32 accumulate
#define MMA16816(d, a, b0, b1) \
    asm volatile("mma.sync.aligned.m16n8k16.row.col.f32.f16.f16.f32 " \
        "{%0,%1,%2,%3},{%4,%5,%6,%7},{%8,%9},{%0,%1,%2,%3};" \
        : "+f"((d)[0]), "+f"((d)[1]), "+f"((d)[2]), "+f"((d)[3]) \
        : "r"((a)[0]), "r"((a)[1]), "r"((a)[2]), "r"((a)[3]), "r"(b0), "r"(b1))

__device__ __forceinline__ float act_sig(float v)  { return 1.0f / (1.0f + __expf(-v)); }
__device__ __forceinline__ float act_tanh(float v) { return 1.0f - 2.0f / (__expf(2.0f * v) + 1.0f); }

// ---------------- convert: x, W -> fp16 ----------------
__global__ __launch_bounds__(256) void convert_kernel(
    const float* __restrict__ x, const float* __restrict__ W)
{
    const size_t MK4 = (size_t)M_SZ * K_SZ / 4;
    const size_t NK4 = (size_t)N_SZ * K_SZ / 4;
    size_t i = (size_t)blockIdx.x * blockDim.x + threadIdx.x;
    if (i >= MK4 + NK4) return;

    const float4* src; uint2* dst; size_t j;
    if (i < MK4) { src = (const float4*)x; dst = (uint2*)g_a16; j = i; }
    else         { src = (const float4*)W; dst = (uint2*)g_b16; j = i - MK4; }

    float4 v = src[j];
    __half2 h01 = __floats2half2_rn(v.x, v.y);
    __half2 h23 = __floats2half2_rn(v.z, v.w);
    uint2 o;
    o.x = *(uint32_t*)&h01; o.y = *(uint32_t*)&h23;
    dst[j] = o;
}

// ---------------- HMMA GEMM: C = A * W^T (+bias), fused activation ----------------
// CTA tile 128x128, BK=32. 4 warps: 2(M) x 2(N), warp tile 64x64.
// 4-stage cp.async pipeline, ONE barrier per chunk, 2 CTAs/SM.
#define LDSM_STRIDE 80
#define TILE_SM 10240            // 128 * 80
#define STAGE_SM (2 * TILE_SM)   // 20480
#define NSTAGE 4
#define GEMM_SMEM (NSTAGE * STAGE_SM) // 81920
#define KCHUNKS 64               // 2048 / 32

__global__ __launch_bounds__(128, 2) void gemm_mma(const float* __restrict__ bias)
{
    extern __shared__ char smem[];
    const uint32_t sb = smem_u32(smem);
    const int tid  = threadIdx.x;
    const int lane = tid & 31;
    const int wid  = tid >> 5;        // 0..3
    const int bx = blockIdx.x;   // N tile 0..31
    const int by = blockIdx.y;   // M tile 0..127

    const int m_off = (wid & 1) * 64;
    const int n_off = (wid >> 1) * 64;

    float acc[4][8][4];
#pragma unroll
    for (int mi = 0; mi < 4; mi++)
#pragma unroll
        for (int ni = 0; ni < 8; ni++)
#pragma unroll
            for (int u = 0; u < 4; u++) acc[mi][ni][u] = 0.0f;

    // ldmatrix per-lane address components
    const uint32_t a_off = (uint32_t)(m_off + (lane & 15)) * LDSM_STRIDE + ((lane >> 4) * 16);
    const uint32_t b_off = (uint32_t)(n_off + (lane & 7) + (((lane >> 3) >> 1) * 8)) * LDSM_STRIDE
                           + (((lane >> 3) & 1) * 16);

    // cp.async mapping: 128 threads, each loads one full row (4 x 16B) per tile
    const int rowL = tid;                // 0..127

    auto load_stage = [&](int st, int c) {
        const uint32_t base = sb + st * STAGE_SM;
        const size_t gA = (size_t)(by * 128 + rowL) * K_SZ + c * 32;
        const size_t gB = (size_t)(bx * 128 + rowL) * K_SZ + c * 32;
        const uint32_t so = base + (uint32_t)rowL * LDSM_STRIDE;
#pragma unroll
        for (int seg = 0; seg < 4; seg++) {
            cp16(so + seg * 16,           g_a16 + gA + seg * 8);
            cp16(so + seg * 16 + TILE_SM, g_b16 + gB + seg * 8);
        }
    };

    auto compute = [&](int st) {
        const uint32_t base = sb + st * STAGE_SM;
#pragma unroll
        for (int s = 0; s < 2; s++) {
            const uint32_t ks = s * 32;
            const uint32_t aB = base + a_off + ks;
            const uint32_t bB = base + TILE_SM + b_off + ks;
            uint32_t a[16], b[16];
#pragma unroll
            for (int nj = 0; nj < 4; nj++)
                LDSM4(b[nj*4+0], b[nj*4+1], b[nj*4+2], b[nj*4+3], bB + nj * 16 * LDSM_STRIDE);
#pragma unroll
            for (int mi = 0; mi < 4; mi++)
                LDSM4(a[mi*4+0], a[mi*4+1], a[mi*4+2], a[mi*4+3], aB + mi * 16 * LDSM_STRIDE);
#pragma unroll
            for (int mi = 0; mi < 4; mi++)
#pragma unroll
                for (int ni = 0; ni < 8; ni++)
                    MMA16816(acc[mi][ni], &a[mi*4], b[(ni>>1)*4 + (ni&1)*2], b[(ni>>1)*4 + (ni&1)*2 + 1]);
        }
    };

    // ---- 4-stage pipelined main loop, single barrier per chunk ----
    // Order per chunk: barrier (protects stage being overwritten), issue next
    // load, THEN wait for this chunk's data — load issue hides in the wait.
    load_stage(0, 0); CP_COMMIT();
    load_stage(1, 1); CP_COMMIT();
    load_stage(2, 2); CP_COMMIT();
    int st = 0;
    for (int c = 0; c < KCHUNKS; c++) {
        // Every warp passing this barrier finished compute(c-1) on stage
        // (c-1)%4 == (c+3)%4, exactly the stage the load below overwrites.
        __syncthreads();
        if (c + 3 < KCHUNKS) {
            load_stage((st + 3) & 3, c + 3); CP_COMMIT();
            CP_WAITN(3);
        } else if (c + 2 < KCHUNKS) { CP_WAITN(2); }
        else if (c + 1 < KCHUNKS)   { CP_WAITN(1); }
        else                        { CP_WAITN(0); }
        compute(st);
        st = (st + 1) & 3;
    }

    // ---- epilogue: bias + activation -> fp16 g_gate16 / g_val16 ----
    const int n0 = bx * 128;
    const bool is_gate = (bx < 16);
    __half* dst = is_gate ? g_gate16 : g_val16;
    const int cadj = is_gate ? 0 : C_SZ;
    const int r_in  = lane >> 2;
    const int cpair = (lane & 3) * 2;

    float bb0[8], bb1[8];
#pragma unroll
    for (int ni = 0; ni < 8; ni++) {
        const int col = n_off + ni * 8 + cpair;
        bb0[ni] = __ldg(bias + n0 + col);
        bb1[ni] = __ldg(bias + n0 + col + 1);
    }

#pragma unroll
    for (int mi = 0; mi < 4; mi++) {
        const int gm = by * 128 + m_off + mi * 16 + r_in;
        __half* row0 = dst + (size_t)gm * C_SZ + (n0 - cadj);
        __half* row1 = row0 + (size_t)8 * C_SZ;
#pragma unroll
        for (int ni = 0; ni < 8; ni++) {
            const int col = n_off + ni * 8 + cpair;
            float v0 = acc[mi][ni][0] + bb0[ni], v1 = acc[mi][ni][1] + bb1[ni];
            float v2 = acc[mi][ni][2] + bb0[ni], v3 = acc[mi][ni][3] + bb1[ni];
            float o0, o1, o2, o3;
            if (is_gate) { o0 = act_sig(v0);  o1 = act_sig(v1);  o2 = act_sig(v2);  o3 = act_sig(v3); }
            else         { o0 = act_tanh(v0); o1 = act_tanh(v1); o2 = act_tanh(v2); o3 = act_tanh(v3); }
            *(__half2*)(row0 + col) = __floats2half2_rn(o0, o1);
            *(__half2*)(row1 + col) = __floats2half2_rn(o2, o3);
        }
    }
}

// ---------------- chunked scan: 3 passes, 2 channels per thread ----------------
__global__ __launch_bounds__(256) void scan_pass1()
{
    const int id = blockIdx.x * blockDim.x + threadIdx.x;
    if (id >= NSEQ2 * SCAN_NCH) return;
    const int chunk = id / NSEQ2;
    const int p     = id - chunk * NSEQ2;    // pair index: seq s = 2p, 2p+1
    const int bb = p >> 10;                  // batch
    const int c  = (p & 1023) * 2;           // channel
    const size_t base = (size_t)bb * T_SZ * C_SZ + (size_t)chunk * SCAN_CH * C_SZ + c;

    const __half2* gp = (const __half2*)(g_gate16 + base);
    const __half2* vp = (const __half2*)(g_val16  + base);

    float2 G = make_float2(1.0f, 1.0f), V = make_float2(0.0f, 0.0f);
#pragma unroll 1
    for (int t = 0; t < SCAN_CH; t += 16) {
        __half2 g[16], v[16];
#pragma unroll
        for (int u = 0; u < 16; u++) {
            g[u] = __ldg(gp + (size_t)(t + u) * (C_SZ / 2));
            v[u] = __ldg(vp + (size_t)(t + u) * (C_SZ / 2));
        }
#pragma unroll
        for (int u = 0; u < 16; u++) {
            float2 gg = __half22float2(g[u]);
            float2 vv = __half22float2(v[u]);
            V.x = fmaf(gg.x, V.x, vv.x);
            V.y = fmaf(gg.y, V.y, vv.y);
            G.x *= gg.x;
            G.y *= gg.y;
        }
    }
    ((float2*)g_Gc)[chunk * NSEQ2 + p] = G;
    ((float2*)g_Vc)[chunk * NSEQ2 + p] = V;
}

__global__ __launch_bounds__(256) void scan_pass2()
{
    const int s = blockIdx.x * blockDim.x + threadIdx.x;
    if (s >= NSEQ) return;
    float G[SCAN_NCH], V[SCAN_NCH];
#pragma unroll
    for (int j = 0; j < SCAN_NCH; j++) {
        G[j] = __ldg(&g_Gc[j * NSEQ + s]);
        V[j] = __ldg(&g_Vc[j * NSEQ + s]);
    }
    float h = 0.0f;
#pragma unroll
    for (int j = 0; j < SCAN_NCH; j++) {
        g_Hin[j * NSEQ + s] = h;
        h = fmaf(G[j], h, V[j]);
    }
}

__global__ __launch_bounds__(256) void scan_pass3(float* __restrict__ out)
{
    const int id = blockIdx.x * blockDim.x + threadIdx.x;
    if (id >= NSEQ2 * SCAN_NCH) return;
    const int chunk = id / NSEQ2;
    const int p     = id - chunk * NSEQ2;
    const int bb = p >> 10;
    const int c  = (p & 1023) * 2;
    const size_t base = (size_t)bb * T_SZ * C_SZ + (size_t)chunk * SCAN_CH * C_SZ + c;

    const __half2* gp = (const __half2*)(g_gate16 + base);
    const __half2* vp = (const __half2*)(g_val16  + base);
    float*         op = out + base;

    float2 h = ((const float2*)g_Hin)[chunk * NSEQ2 + p];
#pragma unroll 1
    for (int t = 0; t < SCAN_CH; t += 16) {
        __half2 g[16], v[16];
#pragma unroll
        for (int u = 0; u < 16; u++) {
            g[u] = __ldg(gp + (size_t)(t + u) * (C_SZ / 2));
            v[u] = __ldg(vp + (size_t)(t + u) * (C_SZ / 2));
        }
#pragma unroll
        for (int u = 0; u < 16; u++) {
            float2 gg = __half22float2(g[u]);
            float2 vv = __half22float2(v[u]);
            h.x = fmaf(gg.x, h.x, vv.x);
            h.y = fmaf(gg.y, h.y, vv.y);
            *(float2*)(op + (size_t)(t + u) * C_SZ) = h;
        }
    }
}

// ---------------- launch ----------------
extern "C" void kernel_launch(void* const* d_in, const int* in_sizes, int n_in,
                              void* d_out, int out_size)
{
    const float* x  = (const float*)d_in[0];  // [B,T,C]
    const float* W  = (const float*)d_in[1];  // [2C,C]
    const float* bi = (const float*)d_in[2];  // [2C]
    float* out = (float*)d_out;               // [B,T,C]

    cudaFuncSetAttribute(gemm_mma, cudaFuncAttributeMaxDynamicSharedMemorySize, GEMM_SMEM);

    const size_t total4 = ((size_t)M_SZ * K_SZ + (size_t)N_SZ * K_SZ) / 4;
    convert_kernel<<<(unsigned)((total4 + 255) / 256), 256>>>(x, W);

    gemm_mma<<<dim3(32, 128), 128, GEMM_SMEM>>>(bi);

    const int nwork = NSEQ2 * SCAN_NCH;      // 131072
    scan_pass1<<<(nwork + 255) / 256, 256>>>();
    scan_pass2<<<(NSEQ + 255) / 256, 256>>>();
    scan_pass3<<<(nwork + 255) / 256, 256>>>(out);
}

// round 12
// speedup vs baseline: 1.1741x; 1.1741x over previous
#include <cuda_runtime.h>
#include <cuda_fp16.h>
#include <cstdint>
#include <math.h>

// ---------------- problem shapes ----------------
#define B_SZ 4
#define T_SZ 4096
#define C_SZ 2048
#define M_SZ (B_SZ * T_SZ)   // 16384
#define N_SZ (2 * C_SZ)      // 4096
#define K_SZ C_SZ            // 2048

// ---------------- device scratch ----------------
__device__ __half g_gate16[(size_t)M_SZ * C_SZ];
__device__ __half g_val16 [(size_t)M_SZ * C_SZ];
__device__ __half g_a16[(size_t)M_SZ * K_SZ];          // x rounded to fp16
__device__ __half g_b16[(size_t)N_SZ * K_SZ];          // W rounded to fp16

// scan chunk summaries: 32 chunks x 8192 sequences (fp32 for precision)
#define SCAN_CH 128
#define SCAN_NCH (T_SZ / SCAN_CH)   // 32
#define NSEQ (B_SZ * C_SZ)          // 8192
#define NSEQ2 (NSEQ / 2)            // 4096 channel-pairs
__device__ float g_Gc [SCAN_NCH * NSEQ];
__device__ float g_Vc [SCAN_NCH * NSEQ];
__device__ float g_Hin[SCAN_NCH * NSEQ];

// ---------------- helpers ----------------
__device__ __forceinline__ uint32_t smem_u32(const void* p) {
    uint32_t a;
    asm("{ .reg .u64 t; cvta.to.shared.u64 t, %1; cvt.u32.u64 %0, t; }" : "=r"(a) : "l"(p));
    return a;
}
__device__ __forceinline__ void cp16(uint32_t dst, const void* src) {
    asm volatile("cp.async.cg.shared.global [%0], [%1], 16;" :: "r"(dst), "l"(src));
}
#define CP_COMMIT() asm volatile("cp.async.commit_group;" ::: "memory")
#define CP_WAITN(n) asm volatile("cp.async.wait_group %0;" :: "n"(n) : "memory")

#define LDSM4(r0, r1, r2, r3, addr) \
    asm volatile("ldmatrix.sync.aligned.m8n8.x4.shared.b16 {%0,%1,%2,%3}, [%4];" \
        : "=r"(r0), "=r"(r1), "=r"(r2), "=r"(r3) : "r"(addr))

// fp16 inputs, fp32 accumulate
#define MMA16816(d, a, b0, b1) \
    asm volatile("mma.sync.aligned.m16n8k16.row.col.f32.f16.f16.f32 " \
        "{%0,%1,%2,%3},{%4,%5,%6,%7},{%8,%9},{%0,%1,%2,%3};" \
        : "+f"((d)[0]), "+f"((d)[1]), "+f"((d)[2]), "+f"((d)[3]) \
        : "r"((a)[0]), "r"((a)[1]), "r"((a)[2]), "r"((a)[3]), "r"(b0), "r"(b1))

__device__ __forceinline__ float act_sig(float v)  { return 1.0f / (1.0f + __expf(-v)); }
__device__ __forceinline__ float act_tanh(float v) { return 1.0f - 2.0f / (__expf(2.0f * v) + 1.0f); }

// ---------------- convert: x, W -> fp16 ----------------
__global__ __launch_bounds__(256) void convert_kernel(
    const float* __restrict__ x, const float* __restrict__ W)
{
    const size_t MK4 = (size_t)M_SZ * K_SZ / 4;
    const size_t NK4 = (size_t)N_SZ * K_SZ / 4;
    size_t i = (size_t)blockIdx.x * blockDim.x + threadIdx.x;
    if (i >= MK4 + NK4) return;

    const float4* src; uint2* dst; size_t j;
    if (i < MK4) { src = (const float4*)x; dst = (uint2*)g_a16; j = i; }
    else         { src = (const float4*)W; dst = (uint2*)g_b16; j = i - MK4; }

    float4 v = src[j];
    __half2 h01 = __floats2half2_rn(v.x, v.y);
    __half2 h23 = __floats2half2_rn(v.z, v.w);
    uint2 o;
    o.x = *(uint32_t*)&h01; o.y = *(uint32_t*)&h23;
    dst[j] = o;
}

// ---------------- HMMA GEMM: C = A * W^T (+bias), fused activation ----------------
// CTA tile 128x128, BK=32. 8 warps: 2(M) x 4(N), warp tile 64x32.
// 5-stage cp.async pipeline, ONE barrier per chunk, 2 CTAs/SM.
#define LDSM_STRIDE 80
#define TILE_SM 10240            // 128 * 80
#define STAGE_SM (2 * TILE_SM)   // 20480
#define NSTAGE 5
#define GEMM_SMEM (NSTAGE * STAGE_SM) // 102400
#define KCHUNKS 64               // 2048 / 32

__global__ __launch_bounds__(256, 2) void gemm_mma(const float* __restrict__ bias)
{
    extern __shared__ char smem[];
    const uint32_t sb = smem_u32(smem);
    const int tid  = threadIdx.x;
    const int lane = tid & 31;
    const int wid  = tid >> 5;
    const int bx = blockIdx.x;   // N tile 0..31
    const int by = blockIdx.y;   // M tile 0..127

    const int m_off = (wid & 1) * 64;
    const int n_off = (wid >> 1) * 32;

    float acc[4][4][4];
#pragma unroll
    for (int mi = 0; mi < 4; mi++)
#pragma unroll
        for (int ni = 0; ni < 4; ni++)
#pragma unroll
            for (int u = 0; u < 4; u++) acc[mi][ni][u] = 0.0f;

    const uint32_t a_off = (uint32_t)(m_off + (lane & 15)) * LDSM_STRIDE + ((lane >> 4) * 16);
    const uint32_t b_off = (uint32_t)(n_off + (lane & 7) + (((lane >> 3) >> 1) * 8)) * LDSM_STRIDE
                           + (((lane >> 3) & 1) * 16);

    const int o0   = 2 * tid;
    const int rowL = o0 >> 2;            // 0..127
    const int segL = o0 & 3;             // 0 or 2 (i adds 0/1)

    auto load_stage = [&](int st, int c) {
        const uint32_t base = sb + st * STAGE_SM;
#pragma unroll
        for (int i = 0; i < 2; i++) {
            const int row = rowL;
            const int seg = segL + i;
            const size_t gA = (size_t)(by * 128 + row) * K_SZ + c * 32 + seg * 8;
            const size_t gB = (size_t)(bx * 128 + row) * K_SZ + c * 32 + seg * 8;
            const uint32_t so = base + (uint32_t)row * LDSM_STRIDE + seg * 16;
            cp16(so,           g_a16 + gA);
            cp16(so + TILE_SM, g_b16 + gB);
        }
    };

    auto compute = [&](int st) {
        const uint32_t base = sb + st * STAGE_SM;
#pragma unroll
        for (int s = 0; s < 2; s++) {
            const uint32_t ks = s * 32;
            const uint32_t aB = base + a_off + ks;
            const uint32_t bB = base + TILE_SM + b_off + ks;
            uint32_t a[16], b[8];
#pragma unroll
            for (int nj = 0; nj < 2; nj++)
                LDSM4(b[nj*4+0], b[nj*4+1], b[nj*4+2], b[nj*4+3], bB + nj * 16 * LDSM_STRIDE);
#pragma unroll
            for (int mi = 0; mi < 4; mi++)
                LDSM4(a[mi*4+0], a[mi*4+1], a[mi*4+2], a[mi*4+3], aB + mi * 16 * LDSM_STRIDE);
#pragma unroll
            for (int mi = 0; mi < 4; mi++)
#pragma unroll
                for (int ni = 0; ni < 4; ni++)
                    MMA16816(acc[mi][ni], &a[mi*4], b[(ni>>1)*4 + (ni&1)*2], b[(ni>>1)*4 + (ni&1)*2 + 1]);
        }
    };

    // ---- 5-stage pipelined main loop, single barrier per chunk ----
    // Per chunk: barrier (protects the stage being overwritten), ISSUE the
    // next load, then wait for this chunk's data — load issue hides in the wait.
    load_stage(0, 0); CP_COMMIT();
    load_stage(1, 1); CP_COMMIT();
    load_stage(2, 2); CP_COMMIT();
    load_stage(3, 3); CP_COMMIT();
    int st = 0;
    for (int c = 0; c < KCHUNKS; c++) {
        // Every warp passing this barrier finished compute(c-1) on stage
        // (c-1)%5 == (c+4)%5, exactly the stage the load below overwrites.
        __syncthreads();
        if (c + 4 < KCHUNKS) {
            load_stage((st + 4) % NSTAGE, c + 4); CP_COMMIT();
            CP_WAITN(4);
        } else if (c + 3 < KCHUNKS) { CP_WAITN(3); }
        else if (c + 2 < KCHUNKS)   { CP_WAITN(2); }
        else if (c + 1 < KCHUNKS)   { CP_WAITN(1); }
        else                        { CP_WAITN(0); }
        compute(st);
        st = (st + 1) % NSTAGE;
    }

    // ---- epilogue: bias + activation -> fp16 g_gate16 / g_val16 ----
    const int n0 = bx * 128;
    const bool is_gate = (bx < 16);
    __half* dst = is_gate ? g_gate16 : g_val16;
    const int cadj = is_gate ? 0 : C_SZ;
    const int r_in  = lane >> 2;
    const int cpair = (lane & 3) * 2;

    float bb0[4], bb1[4];
#pragma unroll
    for (int ni = 0; ni < 4; ni++) {
        const int col = n_off + ni * 8 + cpair;
        bb0[ni] = __ldg(bias + n0 + col);
        bb1[ni] = __ldg(bias + n0 + col + 1);
    }

#pragma unroll
    for (int mi = 0; mi < 4; mi++) {
        const int gm = by * 128 + m_off + mi * 16 + r_in;
        __half* row0 = dst + (size_t)gm * C_SZ + (n0 - cadj);
        __half* row1 = row0 + (size_t)8 * C_SZ;
#pragma unroll
        for (int ni = 0; ni < 4; ni++) {
            const int col = n_off + ni * 8 + cpair;
            float v0 = acc[mi][ni][0] + bb0[ni], v1 = acc[mi][ni][1] + bb1[ni];
            float v2 = acc[mi][ni][2] + bb0[ni], v3 = acc[mi][ni][3] + bb1[ni];
            float o0, o1, o2, o3;
            if (is_gate) { o0 = act_sig(v0);  o1 = act_sig(v1);  o2 = act_sig(v2);  o3 = act_sig(v3); }
            else         { o0 = act_tanh(v0); o1 = act_tanh(v1); o2 = act_tanh(v2); o3 = act_tanh(v3); }
            *(__half2*)(row0 + col) = __floats2half2_rn(o0, o1);
            *(__half2*)(row1 + col) = __floats2half2_rn(o2, o3);
        }
    }
}

// ---------------- chunked scan: 3 passes, 2 channels per thread ----------------
__global__ __launch_bounds__(256) void scan_pass1()
{
    const int id = blockIdx.x * blockDim.x + threadIdx.x;
    if (id >= NSEQ2 * SCAN_NCH) return;
    const int chunk = id / NSEQ2;
    const int p     = id - chunk * NSEQ2;    // pair index: seq s = 2p, 2p+1
    const int bb = p >> 10;                  // batch
    const int c  = (p & 1023) * 2;           // channel
    const size_t base = (size_t)bb * T_SZ * C_SZ + (size_t)chunk * SCAN_CH * C_SZ + c;

    const __half2* gp = (const __half2*)(g_gate16 + base);
    const __half2* vp = (const __half2*)(g_val16  + base);

    float2 G = make_float2(1.0f, 1.0f), V = make_float2(0.0f, 0.0f);
#pragma unroll 1
    for (int t = 0; t < SCAN_CH; t += 16) {
        __half2 g[16], v[16];
#pragma unroll
        for (int u = 0; u < 16; u++) {
            g[u] = __ldg(gp + (size_t)(t + u) * (C_SZ / 2));
            v[u] = __ldg(vp + (size_t)(t + u) * (C_SZ / 2));
        }
#pragma unroll
        for (int u = 0; u < 16; u++) {
            float2 gg = __half22float2(g[u]);
            float2 vv = __half22float2(v[u]);
            V.x = fmaf(gg.x, V.x, vv.x);
            V.y = fmaf(gg.y, V.y, vv.y);
            G.x *= gg.x;
            G.y *= gg.y;
        }
    }
    ((float2*)g_Gc)[chunk * NSEQ2 + p] = G;
    ((float2*)g_Vc)[chunk * NSEQ2 + p] = V;
}

__global__ __launch_bounds__(256) void scan_pass2()
{
    const int s = blockIdx.x * blockDim.x + threadIdx.x;
    if (s >= NSEQ) return;
    float G[SCAN_NCH], V[SCAN_NCH];
#pragma unroll
    for (int j = 0; j < SCAN_NCH; j++) {
        G[j] = __ldg(&g_Gc[j * NSEQ + s]);
        V[j] = __ldg(&g_Vc[j * NSEQ + s]);
    }
    float h = 0.0f;
#pragma unroll
    for (int j = 0; j < SCAN_NCH; j++) {
        g_Hin[j * NSEQ + s] = h;
        h = fmaf(G[j], h, V[j]);
    }
}

__global__ __launch_bounds__(256) void scan_pass3(float* __restrict__ out)
{
    const int id = blockIdx.x * blockDim.x + threadIdx.x;
    if (id >= NSEQ2 * SCAN_NCH) return;
    const int chunk = id / NSEQ2;
    const int p     = id - chunk * NSEQ2;
    const int bb = p >> 10;
    const int c  = (p & 1023) * 2;
    const size_t base = (size_t)bb * T_SZ * C_SZ + (size_t)chunk * SCAN_CH * C_SZ + c;

    const __half2* gp = (const __half2*)(g_gate16 + base);
    const __half2* vp = (const __half2*)(g_val16  + base);
    float*         op = out + base;

    float2 h = ((const float2*)g_Hin)[chunk * NSEQ2 + p];
#pragma unroll 1
    for (int t = 0; t < SCAN_CH; t += 16) {
        __half2 g[16], v[16];
#pragma unroll
        for (int u = 0; u < 16; u++) {
            g[u] = __ldg(gp + (size_t)(t + u) * (C_SZ / 2));
            v[u] = __ldg(vp + (size_t)(t + u) * (C_SZ / 2));
        }
#pragma unroll
        for (int u = 0; u < 16; u++) {
            float2 gg = __half22float2(g[u]);
            float2 vv = __half22float2(v[u]);
            h.x = fmaf(gg.x, h.x, vv.x);
            h.y = fmaf(gg.y, h.y, vv.y);
            *(float2*)(op + (size_t)(t + u) * C_SZ) = h;
        }
    }
}

// ---------------- launch ----------------
extern "C" void kernel_launch(void* const* d_in, const int* in_sizes, int n_in,
                              void* d_out, int out_size)
{
    const float* x  = (const float*)d_in[0];  // [B,T,C]
    const float* W  = (const float*)d_in[1];  // [2C,C]
    const float* bi = (const float*)d_in[2];  // [2C]
    float* out = (float*)d_out;               // [B,T,C]

    cudaFuncSetAttribute(gemm_mma, cudaFuncAttributeMaxDynamicSharedMemorySize, GEMM_SMEM);

    const size_t total4 = ((size_t)M_SZ * K_SZ + (size_t)N_SZ * K_SZ) / 4;
    convert_kernel<<<(unsigned)((total4 + 255) / 256), 256>>>(x, W);

    gemm_mma<<<dim3(32, 128), 256, GEMM_SMEM>>>(bi);

    const int nwork = NSEQ2 * SCAN_NCH;      // 131072
    scan_pass1<<<(nwork + 255) / 256, 256>>>();
    scan_pass2<<<(NSEQ + 255) / 256, 256>>>();
    scan_pass3<<<(nwork + 255) / 256, 256>>>(out);
}

// round 14
// speedup vs baseline: 1.1801x; 1.0051x over previous
#include <cuda_runtime.h>
#include <cuda_fp16.h>
#include <cstdint>
#include <math.h>

// ---------------- problem shapes ----------------
#define B_SZ 4
#define T_SZ 4096
#define C_SZ 2048
#define M_SZ (B_SZ * T_SZ)   // 16384
#define N_SZ (2 * C_SZ)      // 4096
#define K_SZ C_SZ            // 2048

// ---------------- device scratch ----------------
__device__ __half g_gate16[(size_t)M_SZ * C_SZ];
__device__ __half g_val16 [(size_t)M_SZ * C_SZ];
__device__ __half g_a16[(size_t)M_SZ * K_SZ];          // x rounded to fp16
__device__ __half g_b16[(size_t)N_SZ * K_SZ];          // W rounded to fp16

// scan chunk summaries: 32 chunks x 8192 sequences (fp32 for precision)
#define SCAN_CH 128
#define SCAN_NCH (T_SZ / SCAN_CH)   // 32
#define NSEQ (B_SZ * C_SZ)          // 8192
#define NSEQ2 (NSEQ / 2)            // 4096 channel-pairs
__device__ float g_Gc [SCAN_NCH * NSEQ];
__device__ float g_Vc [SCAN_NCH * NSEQ];
__device__ float g_Hin[SCAN_NCH * NSEQ];

// ---------------- helpers ----------------
__device__ __forceinline__ uint32_t smem_u32(const void* p) {
    uint32_t a;
    asm("{ .reg .u64 t; cvta.to.shared.u64 t, %1; cvt.u32.u64 %0, t; }" : "=r"(a) : "l"(p));
    return a;
}
__device__ __forceinline__ void cp16(uint32_t dst, const void* src) {
    asm volatile("cp.async.cg.shared.global [%0], [%1], 16;" :: "r"(dst), "l"(src));
}
#define CP_COMMIT() asm volatile("cp.async.commit_group;" ::: "memory")
#define CP_WAITN(n) asm volatile("cp.async.wait_group %0;" :: "n"(n) : "memory")

#define LDSM4(r0, r1, r2, r3, addr) \
    asm volatile("ldmatrix.sync.aligned.m8n8.x4.shared.b16 {%0,%1,%2,%3}, [%4];" \
        : "=r"(r0), "=r"(r1), "=r"(r2), "=r"(r3) : "r"(addr))

// fp16 inputs, fp32 accumulate
#define MMA16816(d, a, b0, b1) \
    asm volatile("mma.sync.aligned.m16n8k16.row.col.f32.f16.f16.f32 " \
        "{%0,%1,%2,%3},{%4,%5,%6,%7},{%8,%9},{%0,%1,%2,%3};" \
        : "+f"((d)[0]), "+f"((d)[1]), "+f"((d)[2]), "+f"((d)[3]) \
        : "r"((a)[0]), "r"((a)[1]), "r"((a)[2]), "r"((a)[3]), "r"(b0), "r"(b1))

__device__ __forceinline__ float act_sig(float v)  { return 1.0f / (1.0f + __expf(-v)); }
__device__ __forceinline__ float act_tanh(float v) { return 1.0f - 2.0f / (__expf(2.0f * v) + 1.0f); }

// ---------------- convert: x, W -> fp16 ----------------
__global__ __launch_bounds__(256) void convert_kernel(
    const float* __restrict__ x, const float* __restrict__ W)
{
    const size_t MK4 = (size_t)M_SZ * K_SZ / 4;
    const size_t NK4 = (size_t)N_SZ * K_SZ / 4;
    size_t i = (size_t)blockIdx.x * blockDim.x + threadIdx.x;
    if (i >= MK4 + NK4) return;

    const float4* src; uint2* dst; size_t j;
    if (i < MK4) { src = (const float4*)x; dst = (uint2*)g_a16; j = i; }
    else         { src = (const float4*)W; dst = (uint2*)g_b16; j = i - MK4; }

    float4 v = src[j];
    __half2 h01 = __floats2half2_rn(v.x, v.y);
    __half2 h23 = __floats2half2_rn(v.z, v.w);
    uint2 o;
    o.x = *(uint32_t*)&h01; o.y = *(uint32_t*)&h23;
    dst[j] = o;
}

// ---------------- HMMA GEMM: C = A * W^T (+bias), fused activation ----------------
// CTA tile 128x128, BK=32. 8 warps: 2(M) x 4(N), warp tile 64x32.
// 5-stage cp.async pipeline, 2 CTAs/SM.
// SAFE ordering per chunk: wait (own groups) -> barrier (collective: all
// threads' chunk-c data landed) -> issue load(c+4) into the stage whose
// readers all passed the barrier -> compute(c).
#define LDSM_STRIDE 80
#define TILE_SM 10240            // 128 * 80
#define STAGE_SM (2 * TILE_SM)   // 20480
#define NSTAGE 5
#define GEMM_SMEM (NSTAGE * STAGE_SM) // 102400
#define KCHUNKS 64               // 2048 / 32

__global__ __launch_bounds__(256, 2) void gemm_mma(const float* __restrict__ bias)
{
    extern __shared__ char smem[];
    const uint32_t sb = smem_u32(smem);
    const int tid  = threadIdx.x;
    const int lane = tid & 31;
    const int wid  = tid >> 5;
    const int bx = blockIdx.x;   // N tile 0..31
    const int by = blockIdx.y;   // M tile 0..127

    const int m_off = (wid & 1) * 64;
    const int n_off = (wid >> 1) * 32;

    float acc[4][4][4];
#pragma unroll
    for (int mi = 0; mi < 4; mi++)
#pragma unroll
        for (int ni = 0; ni < 4; ni++)
#pragma unroll
            for (int u = 0; u < 4; u++) acc[mi][ni][u] = 0.0f;

    const uint32_t a_off = (uint32_t)(m_off + (lane & 15)) * LDSM_STRIDE + ((lane >> 4) * 16);
    const uint32_t b_off = (uint32_t)(n_off + (lane & 7) + (((lane >> 3) >> 1) * 8)) * LDSM_STRIDE
                           + (((lane >> 3) & 1) * 16);

    const int o0   = 2 * tid;
    const int rowL = o0 >> 2;            // 0..127
    const int segL = o0 & 3;             // 0 or 2 (i adds 0/1)

    auto load_stage = [&](int st, int c) {
        const uint32_t base = sb + st * STAGE_SM;
#pragma unroll
        for (int i = 0; i < 2; i++) {
            const int row = rowL;
            const int seg = segL + i;
            const size_t gA = (size_t)(by * 128 + row) * K_SZ + c * 32 + seg * 8;
            const size_t gB = (size_t)(bx * 128 + row) * K_SZ + c * 32 + seg * 8;
            const uint32_t so = base + (uint32_t)row * LDSM_STRIDE + seg * 16;
            cp16(so,           g_a16 + gA);
            cp16(so + TILE_SM, g_b16 + gB);
        }
    };

    auto compute = [&](int st) {
        const uint32_t base = sb + st * STAGE_SM;
#pragma unroll
        for (int s = 0; s < 2; s++) {
            const uint32_t ks = s * 32;
            const uint32_t aB = base + a_off + ks;
            const uint32_t bB = base + TILE_SM + b_off + ks;
            uint32_t a[16], b[8];
#pragma unroll
            for (int nj = 0; nj < 2; nj++)
                LDSM4(b[nj*4+0], b[nj*4+1], b[nj*4+2], b[nj*4+3], bB + nj * 16 * LDSM_STRIDE);
#pragma unroll
            for (int mi = 0; mi < 4; mi++)
                LDSM4(a[mi*4+0], a[mi*4+1], a[mi*4+2], a[mi*4+3], aB + mi * 16 * LDSM_STRIDE);
#pragma unroll
            for (int mi = 0; mi < 4; mi++)
#pragma unroll
                for (int ni = 0; ni < 4; ni++)
                    MMA16816(acc[mi][ni], &a[mi*4], b[(ni>>1)*4 + (ni&1)*2], b[(ni>>1)*4 + (ni&1)*2 + 1]);
        }
    };

    // ---- 5-stage pipelined main loop ----
    load_stage(0, 0); CP_COMMIT();
    load_stage(1, 1); CP_COMMIT();
    load_stage(2, 2); CP_COMMIT();
    load_stage(3, 3); CP_COMMIT();
    int st = 0;
    for (int c = 0; c < KCHUNKS; c++) {
        // Wait until this thread's group for chunk c completed.
        // At iter c: committed = 4 + c groups; allowing 3 outstanding
        // guarantees groups 0..c done. Tail needs fewer outstanding.
        if (c + 4 <= KCHUNKS)     { CP_WAITN(3); }
        else if (c + 3 <= KCHUNKS){ CP_WAITN(2); }
        else if (c + 2 <= KCHUNKS){ CP_WAITN(1); }
        else                      { CP_WAITN(0); }
        // Barrier: NOW all threads' chunk-c data is in smem. Also: every warp
        // here finished compute(c-1) on stage (c-1)%5 == (c+4)%5 — exactly
        // the stage the load below overwrites.
        __syncthreads();
        if (c + 4 < KCHUNKS) { load_stage((st + 4) % NSTAGE, c + 4); CP_COMMIT(); }
        compute(st);
        st = (st + 1) % NSTAGE;
    }

    // ---- epilogue: bias + activation -> fp16 g_gate16 / g_val16 ----
    const int n0 = bx * 128;
    const bool is_gate = (bx < 16);
    __half* dst = is_gate ? g_gate16 : g_val16;
    const int cadj = is_gate ? 0 : C_SZ;
    const int r_in  = lane >> 2;
    const int cpair = (lane & 3) * 2;

    float bb0[4], bb1[4];
#pragma unroll
    for (int ni = 0; ni < 4; ni++) {
        const int col = n_off + ni * 8 + cpair;
        bb0[ni] = __ldg(bias + n0 + col);
        bb1[ni] = __ldg(bias + n0 + col + 1);
    }

#pragma unroll
    for (int mi = 0; mi < 4; mi++) {
        const int gm = by * 128 + m_off + mi * 16 + r_in;
        __half* row0 = dst + (size_t)gm * C_SZ + (n0 - cadj);
        __half* row1 = row0 + (size_t)8 * C_SZ;
#pragma unroll
        for (int ni = 0; ni < 4; ni++) {
            const int col = n_off + ni * 8 + cpair;
            float v0 = acc[mi][ni][0] + bb0[ni], v1 = acc[mi][ni][1] + bb1[ni];
            float v2 = acc[mi][ni][2] + bb0[ni], v3 = acc[mi][ni][3] + bb1[ni];
            float o0, o1, o2, o3;
            if (is_gate) { o0 = act_sig(v0);  o1 = act_sig(v1);  o2 = act_sig(v2);  o3 = act_sig(v3); }
            else         { o0 = act_tanh(v0); o1 = act_tanh(v1); o2 = act_tanh(v2); o3 = act_tanh(v3); }
            *(__half2*)(row0 + col) = __floats2half2_rn(o0, o1);
            *(__half2*)(row1 + col) = __floats2half2_rn(o2, o3);
        }
    }
}

// ---------------- chunked scan: 3 passes, 2 channels per thread ----------------
__global__ __launch_bounds__(256) void scan_pass1()
{
    const int id = blockIdx.x * blockDim.x + threadIdx.x;
    if (id >= NSEQ2 * SCAN_NCH) return;
    const int chunk = id / NSEQ2;
    const int p     = id - chunk * NSEQ2;    // pair index: seq s = 2p, 2p+1
    const int bb = p >> 10;                  // batch
    const int c  = (p & 1023) * 2;           // channel
    const size_t base = (size_t)bb * T_SZ * C_SZ + (size_t)chunk * SCAN_CH * C_SZ + c;

    const __half2* gp = (const __half2*)(g_gate16 + base);
    const __half2* vp = (const __half2*)(g_val16  + base);

    float2 G = make_float2(1.0f, 1.0f), V = make_float2(0.0f, 0.0f);
#pragma unroll 1
    for (int t = 0; t < SCAN_CH; t += 16) {
        __half2 g[16], v[16];
#pragma unroll
        for (int u = 0; u < 16; u++) {
            g[u] = __ldg(gp + (size_t)(t + u) * (C_SZ / 2));
            v[u] = __ldg(vp + (size_t)(t + u) * (C_SZ / 2));
        }
#pragma unroll
        for (int u = 0; u < 16; u++) {
            float2 gg = __half22float2(g[u]);
            float2 vv = __half22float2(v[u]);
            V.x = fmaf(gg.x, V.x, vv.x);
            V.y = fmaf(gg.y, V.y, vv.y);
            G.x *= gg.x;
            G.y *= gg.y;
        }
    }
    ((float2*)g_Gc)[chunk * NSEQ2 + p] = G;
    ((float2*)g_Vc)[chunk * NSEQ2 + p] = V;
}

__global__ __launch_bounds__(256) void scan_pass2()
{
    const int s = blockIdx.x * blockDim.x + threadIdx.x;
    if (s >= NSEQ) return;
    float G[SCAN_NCH], V[SCAN_NCH];
#pragma unroll
    for (int j = 0; j < SCAN_NCH; j++) {
        G[j] = __ldg(&g_Gc[j * NSEQ + s]);
        V[j] = __ldg(&g_Vc[j * NSEQ + s]);
    }
    float h = 0.0f;
#pragma unroll
    for (int j = 0; j < SCAN_NCH; j++) {
        g_Hin[j * NSEQ + s] = h;
        h = fmaf(G[j], h, V[j]);
    }
}

__global__ __launch_bounds__(256) void scan_pass3(float* __restrict__ out)
{
    const int id = blockIdx.x * blockDim.x + threadIdx.x;
    if (id >= NSEQ2 * SCAN_NCH) return;
    const int chunk = id / NSEQ2;
    const int p     = id - chunk * NSEQ2;
    const int bb = p >> 10;
    const int c  = (p & 1023) * 2;
    const size_t base = (size_t)bb * T_SZ * C_SZ + (size_t)chunk * SCAN_CH * C_SZ + c;

    const __half2* gp = (const __half2*)(g_gate16 + base);
    const __half2* vp = (const __half2*)(g_val16  + base);
    float*         op = out + base;

    float2 h = ((const float2*)g_Hin)[chunk * NSEQ2 + p];
#pragma unroll 1
    for (int t = 0; t < SCAN_CH; t += 16) {
        __half2 g[16], v[16];
#pragma unroll
        for (int u = 0; u < 16; u++) {
            g[u] = __ldg(gp + (size_t)(t + u) * (C_SZ / 2));
            v[u] = __ldg(vp + (size_t)(t + u) * (C_SZ / 2));
        }
#pragma unroll
        for (int u = 0; u < 16; u++) {
            float2 gg = __half22float2(g[u]);
            float2 vv = __half22float2(v[u]);
            h.x = fmaf(gg.x, h.x, vv.x);
            h.y = fmaf(gg.y, h.y, vv.y);
            *(float2*)(op + (size_t)(t + u) * C_SZ) = h;
        }
    }
}

// ---------------- launch ----------------
extern "C" void kernel_launch(void* const* d_in, const int* in_sizes, int n_in,
                              void* d_out, int out_size)
{
    const float* x  = (const float*)d_in[0];  // [B,T,C]
    const float* W  = (const float*)d_in[1];  // [2C,C]
    const float* bi = (const float*)d_in[2];  // [2C]
    float* out = (float*)d_out;               // [B,T,C]

    cudaFuncSetAttribute(gemm_mma, cudaFuncAttributeMaxDynamicSharedMemorySize, GEMM_SMEM);

    const size_t total4 = ((size_t)M_SZ * K_SZ + (size_t)N_SZ * K_SZ) / 4;
    convert_kernel<<<(unsigned)((total4 + 255) / 256), 256>>>(x, W);

    gemm_mma<<<dim3(32, 128), 256, GEMM_SMEM>>>(bi);

    const int nwork = NSEQ2 * SCAN_NCH;      // 131072
    scan_pass1<<<(nwork + 255) / 256, 256>>>();
    scan_pass2<<<(NSEQ + 255) / 256, 256>>>();
    scan_pass3<<<(nwork + 255) / 256, 256>>>(out);
}